// round 2
// baseline (speedup 1.0000x reference)
#include <cuda_runtime.h>
#include <cuda_fp16.h>
#include <cstdint>

#define IN_DIM   1024
#define HDIM     256
#define TILE_M   128
#define KC       64
#define NCHUNK1  (IN_DIM / KC)   // 16
#define NCHUNK2  (HDIM / KC)     // 4
#define NTHREADS 512

// SMEM layout (bytes)
#define OFF_B1     0
#define OFF_B2     1024
#define OFF_BO     2048
#define OFF_ACT1   3072
#define OFF_ACT2   4096
#define OFF_STAGE  8192
#define STAGE_A    16384                  // [128 x 64] fp16
#define STAGE_STRIDE 49152                // A(16K) + B(32K) padded
#define OFF_H      106496                 // 8192 + 2*49152
#define PANEL      16384                  // [128 x 64] fp16 panel
#define SMEM_BYTES 172032                 // OFF_H + 4*PANEL + pad

#define SWZ(o) ((o) ^ (((o) >> 3) & 0x70))

// Packed fp16 weights [N, K] K-major
__device__ __half g_W1h[HDIM * IN_DIM];
__device__ __half g_W2h[HDIM * HDIM];
__device__ __half g_Woh[HDIM * HDIM];

__device__ __forceinline__ uint32_t smem_u32(const void* p) {
    uint32_t a;
    asm("{ .reg .u64 t; cvta.to.shared.u64 t, %1; cvt.u32.u64 %0, t; }"
        : "=r"(a) : "l"(p));
    return a;
}

__device__ __forceinline__ void ldm_x4(uint32_t addr, uint32_t r[4]) {
    asm volatile("ldmatrix.sync.aligned.m8n8.x4.shared.b16 {%0,%1,%2,%3}, [%4];"
                 : "=r"(r[0]), "=r"(r[1]), "=r"(r[2]), "=r"(r[3]) : "r"(addr));
}

__device__ __forceinline__ void mma16816(float c[4], const uint32_t a[4],
                                         const uint32_t b[2]) {
    asm volatile(
        "mma.sync.aligned.m16n8k16.row.col.f32.f16.f16.f32 "
        "{%0,%1,%2,%3}, {%4,%5,%6,%7}, {%8,%9}, {%0,%1,%2,%3};"
        : "+f"(c[0]), "+f"(c[1]), "+f"(c[2]), "+f"(c[3])
        : "r"(a[0]), "r"(a[1]), "r"(a[2]), "r"(a[3]), "r"(b[0]), "r"(b[1]));
}

#define CP_ASYNC16(dst, src) \
    asm volatile("cp.async.cg.shared.global [%0], [%1], 16;" :: "r"(dst), "l"(src))
#define CP_COMMIT() asm volatile("cp.async.commit_group;" ::: "memory")
#define CP_WAIT_ALL() asm volatile("cp.async.wait_group 0;" ::: "memory")

__device__ __forceinline__ float het_act(float z, int id) {
    if (id == 0) return fmaxf(z, 0.0f);
    if (id == 1) return tanhf(z);
    if (id == 2) return 0.5f * z * (1.0f + erff(z * 0.70710678118654752f));
    return 1.0f / (1.0f + expf(-z));
}

// [K,N] fp32 -> [N,K] fp16
__global__ void pack_w(const float* __restrict__ src, __half* __restrict__ dst,
                       int K, int N) {
    __shared__ float t[32][33];
    int n0 = blockIdx.x * 32, k0 = blockIdx.y * 32;
    int tx = threadIdx.x, ty = threadIdx.y;
#pragma unroll
    for (int r = 0; r < 32; r += 8)
        t[ty + r][tx] = src[(size_t)(k0 + ty + r) * N + n0 + tx];
    __syncthreads();
#pragma unroll
    for (int r = 0; r < 32; r += 8)
        dst[(size_t)(n0 + ty + r) * K + k0 + tx] = __float2half_rn(t[tx][ty + r]);
}

struct Frag { float a[2][8][4]; };

// One KC=64 chunk: A tile [128x64] at aBase, B tile [256x64] at bBase
__device__ __forceinline__ void compute_chunk(uint32_t aBase, uint32_t bBase,
                                              int wm, int wn, int lid,
                                              Frag& f) {
    const int a_row = wm * 32 + (lid & 15);
    const int a_koff = (lid & 16) ? 16 : 0;
    const int b_row = wn * 64 + (lid & 7) + ((lid & 16) ? 8 : 0);
    const int b_koff = (lid & 8) ? 16 : 0;
#pragma unroll
    for (int ks = 0; ks < 4; ks++) {
        int k0b = ks * 32;
        uint32_t afrag[2][4];
#pragma unroll
        for (int mb = 0; mb < 2; mb++)
            ldm_x4(aBase + SWZ((a_row + mb * 16) * 128 + k0b + a_koff), afrag[mb]);
#pragma unroll
        for (int nb2 = 0; nb2 < 4; nb2++) {
            uint32_t bfrag[4];
            ldm_x4(bBase + SWZ((b_row + nb2 * 16) * 128 + k0b + b_koff), bfrag);
#pragma unroll
            for (int mb = 0; mb < 2; mb++) {
                mma16816(f.a[mb][2 * nb2],     afrag[mb], bfrag);
                mma16816(f.a[mb][2 * nb2 + 1], afrag[mb], bfrag + 2);
            }
        }
    }
}

__global__ void __launch_bounds__(NTHREADS, 1)
mlp_fused(const float* __restrict__ x,
          const float* __restrict__ b1, const float* __restrict__ b2,
          const float* __restrict__ bo,
          const int* __restrict__ a1, const int* __restrict__ a2,
          float* __restrict__ out) {
    extern __shared__ char smem[];
    uint32_t sb = smem_u32(smem);
    const int tid = threadIdx.x, wid = tid >> 5, lid = tid & 31;
    const int wm = wid & 3, wn = wid >> 2;

    float* b1s = (float*)(smem + OFF_B1);
    float* b2s = (float*)(smem + OFF_B2);
    float* bos = (float*)(smem + OFF_BO);
    int*   a1s = (int*)(smem + OFF_ACT1);
    int*   a2s = (int*)(smem + OFF_ACT2);
    for (int i = tid; i < HDIM; i += NTHREADS) {
        b1s[i] = b1[i]; b2s[i] = b2[i]; bos[i] = bo[i];
        a1s[i] = a1[i]; a2s[i] = a2[i];
    }

    const size_t rowBase = (size_t)blockIdx.x * TILE_M;
    const float* xt = x + rowBase * IN_DIM;

    const uint32_t st0 = sb + OFF_STAGE;
    const uint32_t st1 = sb + OFF_STAGE + STAGE_STRIDE;

    // per-thread copy coords
    const int a_row = tid >> 4, a_q = tid & 15;           // x: 64 floats/row, 4 float4/thread iters
    const int b_row0 = tid >> 3, b_sg = tid & 7;          // W: 8x16B per 128B row

    auto cpasyncB = [&](const __half* W, int ch, uint32_t bBase, int kstride) {
#pragma unroll
        for (int j = 0; j < 4; j++) {
            int row = b_row0 + j * 64;
            CP_ASYNC16(bBase + SWZ(row * 128 + b_sg * 16),
                       W + (size_t)row * kstride + ch * KC + b_sg * 8);
        }
        CP_COMMIT();
    };

    float4 xr[4];
    auto ldgX = [&](int ch) {
#pragma unroll
        for (int j = 0; j < 4; j++) {
            int row = a_row + j * 32;
            xr[j] = *(const float4*)(xt + (size_t)row * IN_DIM + ch * KC + a_q * 4);
        }
    };
    auto stsA = [&](uint32_t aBase) {
#pragma unroll
        for (int j = 0; j < 4; j++) {
            int row = a_row + j * 32;
            __half2 h0 = __floats2half2_rn(xr[j].x, xr[j].y);
            __half2 h1 = __floats2half2_rn(xr[j].z, xr[j].w);
            uint2 u;
            u.x = *reinterpret_cast<unsigned*>(&h0);
            u.y = *reinterpret_cast<unsigned*>(&h1);
            *(uint2*)(smem + (aBase - sb) + SWZ(row * 128 + a_q * 8)) = u;
        }
    };

    Frag f;
#pragma unroll
    for (int mb = 0; mb < 2; mb++)
#pragma unroll
        for (int nb = 0; nb < 8; nb++)
#pragma unroll
            for (int r = 0; r < 4; r++) f.a[mb][nb][r] = 0.0f;

    // ---------------- layer 1 ----------------
    ldgX(0);
    stsA(st0);
    cpasyncB(g_W1h, 0, st0 + STAGE_A, IN_DIM);

    for (int ch = 0; ch < NCHUNK1; ch++) {
        uint32_t cur = (ch & 1) ? st1 : st0;
        uint32_t nxt = (ch & 1) ? st0 : st1;
        CP_WAIT_ALL();
        __syncthreads();
        if (ch + 1 < NCHUNK1) {
            cpasyncB(g_W1h, ch + 1, nxt + STAGE_A, IN_DIM);
            ldgX(ch + 1);
        }
        compute_chunk(cur, cur + STAGE_A, wm, wn, lid, f);
        if (ch + 1 < NCHUNK1) stsA(nxt);
    }

    // prefetch W2 chunk0 (stage0 free: last layer-1 compute used stage1)
    cpasyncB(g_W2h, 0, st0 + STAGE_A, HDIM);

    // epilogue 1 -> h panels
    __syncthreads();
    {
        const int r0 = wm * 32 + (lid >> 2);
        const int cbase = wn * 64 + 2 * (lid & 3);
#pragma unroll
        for (int mb = 0; mb < 2; mb++)
#pragma unroll
            for (int nb = 0; nb < 8; nb++) {
                int col = cbase + nb * 8;
                float bb0 = b1s[col], bb1 = b1s[col + 1];
                int id0 = a1s[col], id1 = a1s[col + 1];
                int panel = col >> 6, cc = col & 63;
                float v0 = het_act(f.a[mb][nb][0] + bb0, id0);
                float v1 = het_act(f.a[mb][nb][1] + bb1, id1);
                float v2 = het_act(f.a[mb][nb][2] + bb0, id0);
                float v3 = het_act(f.a[mb][nb][3] + bb1, id1);
                int rA = r0 + mb * 16, rB = rA + 8;
                *(__half2*)(smem + OFF_H + panel * PANEL + SWZ(rA * 128 + cc * 2)) =
                    __floats2half2_rn(v0, v1);
                *(__half2*)(smem + OFF_H + panel * PANEL + SWZ(rB * 128 + cc * 2)) =
                    __floats2half2_rn(v2, v3);
                f.a[mb][nb][0] = 0.0f; f.a[mb][nb][1] = 0.0f;
                f.a[mb][nb][2] = 0.0f; f.a[mb][nb][3] = 0.0f;
            }
    }
    __syncthreads();

    // ---------------- layer 2 ----------------
    for (int ch = 0; ch < NCHUNK2; ch++) {
        uint32_t cur = (ch & 1) ? st1 : st0;
        uint32_t nxt = (ch & 1) ? st0 : st1;
        CP_WAIT_ALL();
        __syncthreads();
        if (ch + 1 < NCHUNK2) cpasyncB(g_W2h, ch + 1, nxt + STAGE_A, HDIM);
        compute_chunk(sb + OFF_H + ch * PANEL, cur + STAGE_A, wm, wn, lid, f);
    }

    // prefetch Wout chunk0 (stage0 free: layer-2 last compute used stage1)
    cpasyncB(g_Woh, 0, st0 + STAGE_A, HDIM);

    // epilogue 2 -> h panels (all panel reads done before writes)
    __syncthreads();
    {
        const int r0 = wm * 32 + (lid >> 2);
        const int cbase = wn * 64 + 2 * (lid & 3);
#pragma unroll
        for (int mb = 0; mb < 2; mb++)
#pragma unroll
            for (int nb = 0; nb < 8; nb++) {
                int col = cbase + nb * 8;
                float bb0 = b2s[col], bb1 = b2s[col + 1];
                int id0 = a2s[col], id1 = a2s[col + 1];
                int panel = col >> 6, cc = col & 63;
                float v0 = het_act(f.a[mb][nb][0] + bb0, id0);
                float v1 = het_act(f.a[mb][nb][1] + bb1, id1);
                float v2 = het_act(f.a[mb][nb][2] + bb0, id0);
                float v3 = het_act(f.a[mb][nb][3] + bb1, id1);
                int rA = r0 + mb * 16, rB = rA + 8;
                *(__half2*)(smem + OFF_H + panel * PANEL + SWZ(rA * 128 + cc * 2)) =
                    __floats2half2_rn(v0, v1);
                *(__half2*)(smem + OFF_H + panel * PANEL + SWZ(rB * 128 + cc * 2)) =
                    __floats2half2_rn(v2, v3);
                f.a[mb][nb][0] = 0.0f; f.a[mb][nb][1] = 0.0f;
                f.a[mb][nb][2] = 0.0f; f.a[mb][nb][3] = 0.0f;
            }
    }
    __syncthreads();

    // ---------------- layer 3 ----------------
    for (int ch = 0; ch < NCHUNK2; ch++) {
        uint32_t cur = (ch & 1) ? st1 : st0;
        uint32_t nxt = (ch & 1) ? st0 : st1;
        CP_WAIT_ALL();
        __syncthreads();
        if (ch + 1 < NCHUNK2) cpasyncB(g_Woh, ch + 1, nxt + STAGE_A, HDIM);
        compute_chunk(sb + OFF_H + ch * PANEL, cur + STAGE_A, wm, wn, lid, f);
    }

    // output epilogue: acc + bout -> gmem fp32
    {
        const int r0 = wm * 32 + (lid >> 2);
        const int cbase = wn * 64 + 2 * (lid & 3);
#pragma unroll
        for (int mb = 0; mb < 2; mb++)
#pragma unroll
            for (int nb = 0; nb < 8; nb++) {
                int col = cbase + nb * 8;
                float bb0 = bos[col], bb1 = bos[col + 1];
                size_t rA = rowBase + r0 + mb * 16;
                float2 o0 = make_float2(f.a[mb][nb][0] + bb0, f.a[mb][nb][1] + bb1);
                float2 o1 = make_float2(f.a[mb][nb][2] + bb0, f.a[mb][nb][3] + bb1);
                *(float2*)(out + rA * HDIM + col) = o0;
                *(float2*)(out + (rA + 8) * HDIM + col) = o1;
            }
    }
}

extern "C" void kernel_launch(void* const* d_in, const int* in_sizes, int n_in,
                              void* d_out, int out_size) {
    const float* x  = (const float*)d_in[0];
    const float* W1 = (const float*)d_in[1];
    const float* b1 = (const float*)d_in[2];
    const float* W2 = (const float*)d_in[3];
    const float* b2 = (const float*)d_in[4];
    const float* Wo = (const float*)d_in[5];
    const float* bo = (const float*)d_in[6];
    const int*   a1 = (const int*)d_in[7];
    const int*   a2 = (const int*)d_in[8];
    float* out = (float*)d_out;

    int rows = in_sizes[0] / IN_DIM;
    int grid = rows / TILE_M;

    cudaFuncSetAttribute(mlp_fused, cudaFuncAttributeMaxDynamicSharedMemorySize,
                         SMEM_BYTES);

    void *p1, *p2, *p3;
    cudaGetSymbolAddress(&p1, g_W1h);
    cudaGetSymbolAddress(&p2, g_W2h);
    cudaGetSymbolAddress(&p3, g_Woh);

    dim3 tb(32, 8);
    pack_w<<<dim3(HDIM / 32, IN_DIM / 32), tb>>>(W1, (__half*)p1, IN_DIM, HDIM);
    pack_w<<<dim3(HDIM / 32, HDIM / 32),  tb>>>(W2, (__half*)p2, HDIM, HDIM);
    pack_w<<<dim3(HDIM / 32, HDIM / 32),  tb>>>(Wo, (__half*)p3, HDIM, HDIM);

    mlp_fused<<<grid, NTHREADS, SMEM_BYTES>>>(x, b1, b2, bo, a1, a2, out);
}

// round 3
// speedup vs baseline: 1.1583x; 1.1583x over previous
#include <cuda_runtime.h>
#include <cuda_fp16.h>
#include <cstdint>

#define IN_DIM   1024
#define HDIM     256
#define TILE_M   64
#define KC       64
#define NCHUNK1  (IN_DIM / KC)   // 16
#define NCHUNK2  (HDIM / KC)     // 4
#define NTHREADS 256

// SMEM layout (bytes)
#define OFF_B1     0
#define OFF_B2     1024
#define OFF_BO     2048
#define OFF_ACT1   3072
#define OFF_ACT2   4096
#define OFF_STAGE  8192
#define STAGE_A    8192                    // [64 x 64] fp16 A tile size
#define STAGE_B_OFF 8192                   // B tile offset within a stage
#define STAGE_STRIDE 40960                 // A(8K) + B(32K)
#define ST0        (OFF_STAGE)
#define ST1        (OFF_STAGE + STAGE_STRIDE)
#define OFF_H      OFF_STAGE               // h panels ALIAS stage-0 (dead in L2/3)
#define PANEL      8192                    // [64 x 64] fp16 panel
#define SMEM_BYTES (ST1 + STAGE_STRIDE)    // 90112 -> 2 CTAs/SM

#define SWZ(o) ((o) ^ (((o) >> 3) & 0x70))

// Packed fp16 weights [N, K] K-major
__device__ __half g_W1h[HDIM * IN_DIM];
__device__ __half g_W2h[HDIM * HDIM];
__device__ __half g_Woh[HDIM * HDIM];

__device__ __forceinline__ uint32_t smem_u32(const void* p) {
    uint32_t a;
    asm("{ .reg .u64 t; cvta.to.shared.u64 t, %1; cvt.u32.u64 %0, t; }"
        : "=r"(a) : "l"(p));
    return a;
}

__device__ __forceinline__ void ldm_x4(uint32_t addr, uint32_t r[4]) {
    asm volatile("ldmatrix.sync.aligned.m8n8.x4.shared.b16 {%0,%1,%2,%3}, [%4];"
                 : "=r"(r[0]), "=r"(r[1]), "=r"(r[2]), "=r"(r[3]) : "r"(addr));
}

__device__ __forceinline__ void mma16816(float c[4], const uint32_t a[4],
                                         const uint32_t b[2]) {
    asm volatile(
        "mma.sync.aligned.m16n8k16.row.col.f32.f16.f16.f32 "
        "{%0,%1,%2,%3}, {%4,%5,%6,%7}, {%8,%9}, {%0,%1,%2,%3};"
        : "+f"(c[0]), "+f"(c[1]), "+f"(c[2]), "+f"(c[3])
        : "r"(a[0]), "r"(a[1]), "r"(a[2]), "r"(a[3]), "r"(b[0]), "r"(b[1]));
}

#define CP_ASYNC16(dst, src) \
    asm volatile("cp.async.cg.shared.global [%0], [%1], 16;" :: "r"(dst), "l"(src))
#define CP_COMMIT() asm volatile("cp.async.commit_group;" ::: "memory")
#define CP_WAIT_ALL() asm volatile("cp.async.wait_group 0;" ::: "memory")

__device__ __forceinline__ float het_act(float z, int id) {
    if (id == 0) return fmaxf(z, 0.0f);
    if (id == 1) return tanhf(z);
    if (id == 2) return 0.5f * z * (1.0f + erff(z * 0.70710678118654752f));
    return __fdividef(1.0f, 1.0f + __expf(-z));
}

// [K,N] fp32 -> [N,K] fp16
__global__ void pack_w(const float* __restrict__ src, __half* __restrict__ dst,
                       int K, int N) {
    __shared__ float t[32][33];
    int n0 = blockIdx.x * 32, k0 = blockIdx.y * 32;
    int tx = threadIdx.x, ty = threadIdx.y;
#pragma unroll
    for (int r = 0; r < 32; r += 8)
        t[ty + r][tx] = src[(size_t)(k0 + ty + r) * N + n0 + tx];
    __syncthreads();
#pragma unroll
    for (int r = 0; r < 32; r += 8)
        dst[(size_t)(n0 + ty + r) * K + k0 + tx] = __float2half_rn(t[tx][ty + r]);
}

struct Frag { float a[2][8][4]; };

// One KC=64 chunk: A tile [64x64] at aBase, B tile [256x64] at bBase
__device__ __forceinline__ void compute_chunk(uint32_t aBase, uint32_t bBase,
                                              int wm, int wn, int lid,
                                              Frag& f) {
    const int a_row = wm * 32 + (lid & 15);
    const int a_koff = (lid & 16) ? 16 : 0;
    const int b_row = wn * 64 + (lid & 7) + ((lid & 16) ? 8 : 0);
    const int b_koff = (lid & 8) ? 16 : 0;
#pragma unroll
    for (int ks = 0; ks < 4; ks++) {
        int k0b = ks * 32;
        uint32_t afrag[2][4];
#pragma unroll
        for (int mb = 0; mb < 2; mb++)
            ldm_x4(aBase + SWZ((a_row + mb * 16) * 128 + k0b + a_koff), afrag[mb]);
#pragma unroll
        for (int nb2 = 0; nb2 < 4; nb2++) {
            uint32_t bfrag[4];
            ldm_x4(bBase + SWZ((b_row + nb2 * 16) * 128 + k0b + b_koff), bfrag);
#pragma unroll
            for (int mb = 0; mb < 2; mb++) {
                mma16816(f.a[mb][2 * nb2],     afrag[mb], bfrag);
                mma16816(f.a[mb][2 * nb2 + 1], afrag[mb], bfrag + 2);
            }
        }
    }
}

__global__ void __launch_bounds__(NTHREADS, 2)
mlp_fused(const float* __restrict__ x,
          const float* __restrict__ b1, const float* __restrict__ b2,
          const float* __restrict__ bo,
          const int* __restrict__ a1, const int* __restrict__ a2,
          float* __restrict__ out) {
    extern __shared__ char smem[];
    uint32_t sb = smem_u32(smem);
    const int tid = threadIdx.x, wid = tid >> 5, lid = tid & 31;
    const int wm = wid & 1, wn = wid >> 1;   // 2 x 4 warp grid, warp tile 32x64

    float* b1s = (float*)(smem + OFF_B1);
    float* b2s = (float*)(smem + OFF_B2);
    float* bos = (float*)(smem + OFF_BO);
    int*   a1s = (int*)(smem + OFF_ACT1);
    int*   a2s = (int*)(smem + OFF_ACT2);
    for (int i = tid; i < HDIM; i += NTHREADS) {
        b1s[i] = b1[i]; b2s[i] = b2[i]; bos[i] = bo[i];
        a1s[i] = a1[i]; a2s[i] = a2[i];
    }

    const size_t rowBase = (size_t)blockIdx.x * TILE_M;
    const float* xt = x + rowBase * IN_DIM;

    // copy coords
    const int a_row = tid >> 4, a_q = tid & 15;   // A: [64 rows x 16 float4]
    const int b_row0 = tid >> 3, b_sg = tid & 7;  // B: 8 x 16B per 128B row

    auto cpasyncB = [&](const __half* W, int ch, uint32_t bBase, int kstride) {
#pragma unroll
        for (int j = 0; j < 8; j++) {
            int row = b_row0 + j * 32;
            CP_ASYNC16(bBase + SWZ(row * 128 + b_sg * 16),
                       W + (size_t)row * kstride + ch * KC + b_sg * 8);
        }
        CP_COMMIT();
    };

    float4 xr[4];
    auto ldgX = [&](int ch) {
#pragma unroll
        for (int j = 0; j < 4; j++) {
            int row = a_row + j * 16;
            xr[j] = *(const float4*)(xt + (size_t)row * IN_DIM + ch * KC + a_q * 4);
        }
    };
    auto stsA = [&](uint32_t aOff) {
#pragma unroll
        for (int j = 0; j < 4; j++) {
            int row = a_row + j * 16;
            __half2 h0 = __floats2half2_rn(xr[j].x, xr[j].y);
            __half2 h1 = __floats2half2_rn(xr[j].z, xr[j].w);
            uint2 u;
            u.x = *reinterpret_cast<unsigned*>(&h0);
            u.y = *reinterpret_cast<unsigned*>(&h1);
            *(uint2*)(smem + aOff + SWZ(row * 128 + a_q * 8)) = u;
        }
    };

    Frag f;
#pragma unroll
    for (int mb = 0; mb < 2; mb++)
#pragma unroll
        for (int nb = 0; nb < 8; nb++)
#pragma unroll
            for (int r = 0; r < 4; r++) f.a[mb][nb][r] = 0.0f;

    // ---------------- layer 1 (double-buffered stages) ----------------
    ldgX(0);
    stsA(ST0);
    cpasyncB(g_W1h, 0, sb + ST0 + STAGE_B_OFF, IN_DIM);

    for (int ch = 0; ch < NCHUNK1; ch++) {
        uint32_t curO = (ch & 1) ? ST1 : ST0;
        uint32_t nxtO = (ch & 1) ? ST0 : ST1;
        CP_WAIT_ALL();
        __syncthreads();
        if (ch + 1 < NCHUNK1) {
            cpasyncB(g_W1h, ch + 1, sb + nxtO + STAGE_B_OFF, IN_DIM);
            ldgX(ch + 1);
        }
        compute_chunk(sb + curO, sb + curO + STAGE_B_OFF, wm, wn, lid, f);
        if (ch + 1 < NCHUNK1) stsA(nxtO);
    }
    __syncthreads();                       // all done with ST1 before reuse
    cpasyncB(g_W2h, 0, sb + ST1 + STAGE_B_OFF, HDIM);

    // epilogue 1 -> h panels (alias over stage-0; stage-0 dead after sync)
    {
        const int r0 = wm * 32 + (lid >> 2);
        const int cbase = wn * 64 + 2 * (lid & 3);
#pragma unroll
        for (int mb = 0; mb < 2; mb++)
#pragma unroll
            for (int nb = 0; nb < 8; nb++) {
                int col = cbase + nb * 8;
                float bb0 = b1s[col], bb1 = b1s[col + 1];
                int id0 = a1s[col], id1 = a1s[col + 1];
                int panel = col >> 6, cc = col & 63;
                float v0 = het_act(f.a[mb][nb][0] + bb0, id0);
                float v1 = het_act(f.a[mb][nb][1] + bb1, id1);
                float v2 = het_act(f.a[mb][nb][2] + bb0, id0);
                float v3 = het_act(f.a[mb][nb][3] + bb1, id1);
                int rA = r0 + mb * 16, rB = rA + 8;
                *(__half2*)(smem + OFF_H + panel * PANEL + SWZ(rA * 128 + cc * 2)) =
                    __floats2half2_rn(v0, v1);
                *(__half2*)(smem + OFF_H + panel * PANEL + SWZ(rB * 128 + cc * 2)) =
                    __floats2half2_rn(v2, v3);
                f.a[mb][nb][0] = 0.0f; f.a[mb][nb][1] = 0.0f;
                f.a[mb][nb][2] = 0.0f; f.a[mb][nb][3] = 0.0f;
            }
    }
    __syncthreads();

    // ---------------- layer 2 (single B buffer in ST1, L2-resident W) ------
    for (int ch = 0; ch < NCHUNK2; ch++) {
        CP_WAIT_ALL();
        __syncthreads();
        compute_chunk(sb + OFF_H + ch * PANEL, sb + ST1 + STAGE_B_OFF, wm, wn, lid, f);
        __syncthreads();
        if (ch + 1 < NCHUNK2)
            cpasyncB(g_W2h, ch + 1, sb + ST1 + STAGE_B_OFF, HDIM);
    }
    cpasyncB(g_Woh, 0, sb + ST1 + STAGE_B_OFF, HDIM);

    // epilogue 2 -> h panels (reads f regs only; panels safe to overwrite)
    {
        const int r0 = wm * 32 + (lid >> 2);
        const int cbase = wn * 64 + 2 * (lid & 3);
#pragma unroll
        for (int mb = 0; mb < 2; mb++)
#pragma unroll
            for (int nb = 0; nb < 8; nb++) {
                int col = cbase + nb * 8;
                float bb0 = b2s[col], bb1 = b2s[col + 1];
                int id0 = a2s[col], id1 = a2s[col + 1];
                int panel = col >> 6, cc = col & 63;
                float v0 = het_act(f.a[mb][nb][0] + bb0, id0);
                float v1 = het_act(f.a[mb][nb][1] + bb1, id1);
                float v2 = het_act(f.a[mb][nb][2] + bb0, id0);
                float v3 = het_act(f.a[mb][nb][3] + bb1, id1);
                int rA = r0 + mb * 16, rB = rA + 8;
                *(__half2*)(smem + OFF_H + panel * PANEL + SWZ(rA * 128 + cc * 2)) =
                    __floats2half2_rn(v0, v1);
                *(__half2*)(smem + OFF_H + panel * PANEL + SWZ(rB * 128 + cc * 2)) =
                    __floats2half2_rn(v2, v3);
                f.a[mb][nb][0] = 0.0f; f.a[mb][nb][1] = 0.0f;
                f.a[mb][nb][2] = 0.0f; f.a[mb][nb][3] = 0.0f;
            }
    }
    __syncthreads();

    // ---------------- layer 3 (single B buffer in ST1) ----------------
    for (int ch = 0; ch < NCHUNK2; ch++) {
        CP_WAIT_ALL();
        __syncthreads();
        compute_chunk(sb + OFF_H + ch * PANEL, sb + ST1 + STAGE_B_OFF, wm, wn, lid, f);
        __syncthreads();
        if (ch + 1 < NCHUNK2)
            cpasyncB(g_Woh, ch + 1, sb + ST1 + STAGE_B_OFF, HDIM);
    }

    // output epilogue: acc + bout -> gmem fp32
    {
        const int r0 = wm * 32 + (lid >> 2);
        const int cbase = wn * 64 + 2 * (lid & 3);
#pragma unroll
        for (int mb = 0; mb < 2; mb++)
#pragma unroll
            for (int nb = 0; nb < 8; nb++) {
                int col = cbase + nb * 8;
                float bb0 = bos[col], bb1 = bos[col + 1];
                size_t rA = rowBase + r0 + mb * 16;
                float2 o0 = make_float2(f.a[mb][nb][0] + bb0, f.a[mb][nb][1] + bb1);
                float2 o1 = make_float2(f.a[mb][nb][2] + bb0, f.a[mb][nb][3] + bb1);
                *(float2*)(out + rA * HDIM + col) = o0;
                *(float2*)(out + (rA + 8) * HDIM + col) = o1;
            }
    }
}

extern "C" void kernel_launch(void* const* d_in, const int* in_sizes, int n_in,
                              void* d_out, int out_size) {
    const float* x  = (const float*)d_in[0];
    const float* W1 = (const float*)d_in[1];
    const float* b1 = (const float*)d_in[2];
    const float* W2 = (const float*)d_in[3];
    const float* b2 = (const float*)d_in[4];
    const float* Wo = (const float*)d_in[5];
    const float* bo = (const float*)d_in[6];
    const int*   a1 = (const int*)d_in[7];
    const int*   a2 = (const int*)d_in[8];
    float* out = (float*)d_out;

    int rows = in_sizes[0] / IN_DIM;
    int grid = rows / TILE_M;

    cudaFuncSetAttribute(mlp_fused, cudaFuncAttributeMaxDynamicSharedMemorySize,
                         SMEM_BYTES);

    void *p1, *p2, *p3;
    cudaGetSymbolAddress(&p1, g_W1h);
    cudaGetSymbolAddress(&p2, g_W2h);
    cudaGetSymbolAddress(&p3, g_Woh);

    dim3 tb(32, 8);
    pack_w<<<dim3(HDIM / 32, IN_DIM / 32), tb>>>(W1, (__half*)p1, IN_DIM, HDIM);
    pack_w<<<dim3(HDIM / 32, HDIM / 32),  tb>>>(W2, (__half*)p2, HDIM, HDIM);
    pack_w<<<dim3(HDIM / 32, HDIM / 32),  tb>>>(Wo, (__half*)p3, HDIM, HDIM);

    mlp_fused<<<grid, NTHREADS, SMEM_BYTES>>>(x, b1, b2, bo, a1, a2, out);
}